// round 1
// baseline (speedup 1.0000x reference)
#include <cuda_runtime.h>

#define BB 4
#define HH 128
#define WW 128
#define CC 1024
#define NB 8
#define BS 128
#define HID 256
#define LAM 0.01f

#define NTOT (BB*HH*WW*CC)   // 67,108,864

// Scratch (device .bss — no allocation)
__device__ float g_buf1[NTOT];
__device__ float g_buf2[NTOT];
__device__ float g_cas[128*128];
__device__ float g_w1s[NB*BS*HID];
__device__ float g_b1s[NB*HID];
__device__ float g_w2s[NB*HID*BS];
__device__ float g_b2s[NB*BS];

// ---------------------------------------------------------------------------
// prep: build cas matrix, fold w1[0]+w1[1], w2[0]+w2[1], copy b1[0], b2[0]
// ---------------------------------------------------------------------------
__global__ void prep_kernel(const float* __restrict__ w1, const float* __restrict__ b1,
                            const float* __restrict__ w2, const float* __restrict__ b2) {
    int t = blockIdx.x * blockDim.x + threadIdx.x;
    if (t < 128*128) {
        int k = t >> 7, n = t & 127;
        float s, c;
        // angle = 2*pi*k*n/128 = pi * ((k*n mod 128)/64)
        sincospif((float)((k*n) & 127) * (1.0f/64.0f), &s, &c);
        g_cas[t] = c + s;
    }
    if (t < NB*BS*HID) {
        g_w1s[t] = w1[t] + w1[NB*BS*HID + t];
        g_w2s[t] = w2[t] + w2[NB*HID*BS + t];
    }
    if (t < NB*HID) g_b1s[t] = b1[t];
    if (t < NB*BS)  g_b2s[t] = b2[t];
}

// ---------------------------------------------------------------------------
// casmul: Out[b, m, n] = scale * sum_k cas[m,k] * In[b, k, n]  (+ add[b,m,n])
// In/Out layout: element (b,k,n) at b*128*ncols + k*ncols + n   (n contiguous)
// grid: (ncols/64, nbatch), 256 threads, dyn smem = 98304 B
// ---------------------------------------------------------------------------
extern __shared__ float sm_[];

__global__ __launch_bounds__(256, 2)
void casmul_kernel(const float* __restrict__ in, float* __restrict__ out,
                   const float* __restrict__ addsrc, float scale, int ncols) {
    float* casS = sm_;            // 128*128 floats (cas is symmetric -> [k][m])
    float* bS   = sm_ + 16384;    // 128*64 floats: In[k][n-tile]
    const int tid = threadIdx.x;
    const size_t base = (size_t)blockIdx.y * 128u * (size_t)ncols;
    const int n0 = blockIdx.x * 64;

    // load cas (16384 floats, 64 per thread)
    #pragma unroll
    for (int i = 0; i < 16; i++) {
        *(float4*)&casS[i*1024 + tid*4] = *(const float4*)&g_cas[i*1024 + tid*4];
    }
    // load B tile: 128 x 64 = 2048 float4
    #pragma unroll
    for (int it = 0; it < 8; it++) {
        int idx = it*256 + tid;
        int k = idx >> 4, nn = (idx & 15) << 2;
        *(float4*)&bS[k*64 + nn] =
            *(const float4*)&in[base + (size_t)k * (size_t)ncols + n0 + nn];
    }
    __syncthreads();

    const int tx = tid & 15, ty = tid >> 4;
    const int m0 = ty * 8, c0 = tx * 4;

    float acc[8][4];
    #pragma unroll
    for (int i = 0; i < 8; i++)
        #pragma unroll
        for (int j = 0; j < 4; j++) acc[i][j] = 0.f;

    #pragma unroll 4
    for (int k = 0; k < 128; k++) {
        float4 bv = *(const float4*)&bS[k*64 + c0];
        float4 a0 = *(const float4*)&casS[k*128 + m0];
        float4 a1 = *(const float4*)&casS[k*128 + m0 + 4];
        float a[8] = {a0.x, a0.y, a0.z, a0.w, a1.x, a1.y, a1.z, a1.w};
        #pragma unroll
        for (int i = 0; i < 8; i++) {
            acc[i][0] += a[i] * bv.x;
            acc[i][1] += a[i] * bv.y;
            acc[i][2] += a[i] * bv.z;
            acc[i][3] += a[i] * bv.w;
        }
    }

    #pragma unroll
    for (int i = 0; i < 8; i++) {
        size_t o = base + (size_t)(m0 + i) * (size_t)ncols + n0 + c0;
        float4 v;
        v.x = acc[i][0] * scale; v.y = acc[i][1] * scale;
        v.z = acc[i][2] * scale; v.w = acc[i][3] * scale;
        if (addsrc) {
            float4 ad = *(const float4*)&addsrc[o];
            v.x += ad.x; v.y += ad.y; v.z += ad.z; v.w += ad.w;
        }
        *(float4*)&out[o] = v;
    }
}

// ---------------------------------------------------------------------------
// mlp: per pixel-row r, per channel-block blk:
//   o1 = relu(in[r,blk,:] @ W1s[blk] + b1s[blk])       (128 -> 256)
//   o2 = o1 @ W2s[blk] + b2s[blk]                      (256 -> 128)
//   out = softthresh(o2, LAM)
// grid: (65536/64, 8), 256 threads, dyn smem = 100352 B
// ---------------------------------------------------------------------------
__global__ __launch_bounds__(256, 2)
void mlp_kernel(const float* __restrict__ in, float* __restrict__ out) {
    float* inS = sm_;             // 64 x 132 (pad)
    float* o1S = sm_ + 64*132;    // 64 x 260 (pad)
    const int tid = threadIdx.x;
    const int blk = blockIdx.y;
    const size_t row0 = (size_t)blockIdx.x * 64u;

    // load input tile 64 x 128
    #pragma unroll
    for (int it = 0; it < 8; it++) {
        int r  = it*8 + (tid >> 5);
        int c4 = (tid & 31) << 2;
        *(float4*)&inS[r*132 + c4] =
            *(const float4*)&in[(row0 + r) * CC + blk*BS + c4];
    }
    __syncthreads();

    const int tx = tid & 15, ty = tid >> 4;
    const float* w1p = g_w1s + blk*BS*HID;

    // GEMM1: [64,128] @ [128,256] + bias, relu -> o1S
    #pragma unroll
    for (int sub = 0; sub < 4; sub++) {
        const int nidx = sub*64 + tx*4;
        float acc[4][4];
        #pragma unroll
        for (int i = 0; i < 4; i++)
            #pragma unroll
            for (int j = 0; j < 4; j++) acc[i][j] = 0.f;
        #pragma unroll 4
        for (int k = 0; k < 128; k++) {
            float4 wv = *(const float4*)&w1p[k*HID + nidx];
            #pragma unroll
            for (int i = 0; i < 4; i++) {
                float a = inS[(ty*4 + i)*132 + k];
                acc[i][0] += a * wv.x; acc[i][1] += a * wv.y;
                acc[i][2] += a * wv.z; acc[i][3] += a * wv.w;
            }
        }
        float4 bb = *(const float4*)&g_b1s[blk*HID + nidx];
        #pragma unroll
        for (int i = 0; i < 4; i++) {
            float4 v;
            v.x = fmaxf(acc[i][0] + bb.x, 0.f);
            v.y = fmaxf(acc[i][1] + bb.y, 0.f);
            v.z = fmaxf(acc[i][2] + bb.z, 0.f);
            v.w = fmaxf(acc[i][3] + bb.w, 0.f);
            *(float4*)&o1S[(ty*4 + i)*260 + nidx] = v;
        }
    }
    __syncthreads();

    // GEMM2: [64,256] @ [256,128] + bias, softthresh -> out
    const float* w2p = g_w2s + blk*HID*BS;
    #pragma unroll
    for (int sub = 0; sub < 2; sub++) {
        const int nidx = sub*64 + tx*4;
        float acc[4][4];
        #pragma unroll
        for (int i = 0; i < 4; i++)
            #pragma unroll
            for (int j = 0; j < 4; j++) acc[i][j] = 0.f;
        #pragma unroll 4
        for (int k = 0; k < 256; k++) {
            float4 wv = *(const float4*)&w2p[k*BS + nidx];
            #pragma unroll
            for (int i = 0; i < 4; i++) {
                float a = o1S[(ty*4 + i)*260 + k];
                acc[i][0] += a * wv.x; acc[i][1] += a * wv.y;
                acc[i][2] += a * wv.z; acc[i][3] += a * wv.w;
            }
        }
        float4 bb = *(const float4*)&g_b2s[blk*BS + nidx];
        #pragma unroll
        for (int i = 0; i < 4; i++) {
            float vv[4] = {acc[i][0] + bb.x, acc[i][1] + bb.y,
                           acc[i][2] + bb.z, acc[i][3] + bb.w};
            float4 v;
            float* vp = &v.x;
            #pragma unroll
            for (int j = 0; j < 4; j++) {
                float z = vv[j];
                vp[j] = (z > LAM) ? (z - LAM) : ((z < -LAM) ? (z + LAM) : 0.f);
            }
            *(float4*)&out[(row0 + ty*4 + i) * CC + blk*BS + nidx] = v;
        }
    }
}

// ---------------------------------------------------------------------------
extern "C" void kernel_launch(void* const* d_in, const int* in_sizes, int n_in,
                              void* d_out, int out_size) {
    const float* x  = (const float*)d_in[0];
    const float* w1 = (const float*)d_in[1];
    const float* b1 = (const float*)d_in[2];
    const float* w2 = (const float*)d_in[3];
    const float* b2 = (const float*)d_in[4];
    float* out = (float*)d_out;

    void *p1, *p2;
    cudaGetSymbolAddress(&p1, g_buf1);
    cudaGetSymbolAddress(&p2, g_buf2);
    float* buf1 = (float*)p1;
    float* buf2 = (float*)p2;

    const int CAS_SMEM = (16384 + 128*64) * 4;          // 98304
    const int MLP_SMEM = (64*132 + 64*260) * 4;         // 100352
    cudaFuncSetAttribute(casmul_kernel, cudaFuncAttributeMaxDynamicSharedMemorySize, CAS_SMEM);
    cudaFuncSetAttribute(mlp_kernel,    cudaFuncAttributeMaxDynamicSharedMemorySize, MLP_SMEM);

    // fold weights + build cas
    prep_kernel<<<1024, 256>>>(w1, b1, w2, b2);

    // forward DHT: along W (batch = B*H = 512, ncols = C), then along H (batch = B, ncols = W*C)
    casmul_kernel<<<dim3(CC/64, BB*HH), 256, CAS_SMEM>>>(x,    buf1, nullptr, 1.0f, CC);
    casmul_kernel<<<dim3(WW*CC/64, BB), 256, CAS_SMEM>>>(buf1, buf2, nullptr, 1.0f, WW*CC);

    // block MLP + soft threshold
    mlp_kernel<<<dim3(BB*HH*WW/64, NB), 256, MLP_SMEM>>>(buf2, buf1);

    // inverse DHT (same transform), scale 1/(H*W) and add residual on last pass
    casmul_kernel<<<dim3(CC/64, BB*HH), 256, CAS_SMEM>>>(buf1, buf2, nullptr, 1.0f, CC);
    casmul_kernel<<<dim3(WW*CC/64, BB), 256, CAS_SMEM>>>(buf2, out, x, 1.0f/(HH*WW), WW*CC);
}

// round 2
// speedup vs baseline: 2.5733x; 2.5733x over previous
#include <cuda_runtime.h>
#include <stdint.h>

#define BB 4
#define HH 128
#define WW 128
#define CC 1024
#define NB 8
#define BS 128
#define HID 256
#define LAM 0.01f
#define NTOT (BB*HH*WW*CC)   // 67,108,864

// ---------------- scratch (device .bss, no allocation) ----------------
__device__ __align__(128) float g_buf1[NTOT];
__device__ __align__(128) float g_buf2[NTOT];
// cas matrix pre-permuted into mma A-fragment layout (tf32 bits):
// frag index t = (mt*16 + ks)*32 + lane ; 4 regs each
__device__ __align__(16) uint32_t g_casP[8*16*32*4];
__device__ __align__(16) uint32_t g_w1s[NB*BS*HID];   // folded, tf32 bits [blk][i=128][o=256]
__device__ __align__(16) uint32_t g_w2s[NB*HID*BS];   // folded, tf32 bits [blk][o=256][i=128]
__device__ float g_b1s[NB*HID];
__device__ float g_b2s[NB*BS];

// ---------------- helpers ----------------
__device__ __forceinline__ uint32_t f2tf(float f) {
    uint32_t u; asm("cvt.rna.tf32.f32 %0, %1;" : "=r"(u) : "f"(f)); return u;
}
__device__ __forceinline__ void mma8(float* c, uint32_t a0, uint32_t a1, uint32_t a2, uint32_t a3,
                                     uint32_t b0, uint32_t b1) {
    asm volatile("mma.sync.aligned.m16n8k8.row.col.f32.tf32.tf32.f32 "
                 "{%0,%1,%2,%3}, {%4,%5,%6,%7}, {%8,%9}, {%0,%1,%2,%3};"
                 : "+f"(c[0]), "+f"(c[1]), "+f"(c[2]), "+f"(c[3])
                 : "r"(a0), "r"(a1), "r"(a2), "r"(a3), "r"(b0), "r"(b1));
}

// ---------------- prep: cas fragments + folded tf32 weights ----------------
__device__ __forceinline__ float casv(int m, int k) {
    float s, c;
    sincospif((float)((m * k) & 127) * (1.0f/64.0f), &s, &c);
    return c + s;
}

__global__ void prep_kernel(const float* __restrict__ w1, const float* __restrict__ b1,
                            const float* __restrict__ w2, const float* __restrict__ b2) {
    int t = blockIdx.x * blockDim.x + threadIdx.x;
    if (t < 8*16*32) {
        int lane = t & 31, ks = (t >> 5) & 15, mt = t >> 9;
        int g = lane >> 2, kk = ks*8 + (lane & 3);
        int m0 = mt*16 + g;
        uint32_t* d = &g_casP[t*4];
        d[0] = f2tf(casv(m0,     kk));
        d[1] = f2tf(casv(m0 + 8, kk));
        d[2] = f2tf(casv(m0,     kk + 4));
        d[3] = f2tf(casv(m0 + 8, kk + 4));
    }
    if (t < NB*BS*HID) {
        g_w1s[t] = f2tf(w1[t] + w1[NB*BS*HID + t]);
        g_w2s[t] = f2tf(w2[t] + w2[NB*HID*BS + t]);
    }
    if (t < NB*HID) g_b1s[t] = b1[t];
    if (t < NB*BS)  g_b2s[t] = b2[t];
}

// ---------------------------------------------------------------------------
// casmul_tc: OUT[batch, m, n] = scale * sum_k cas[m,k] IN[batch, k, n] (+ add)
// CTA tile: 128m x 128n, k=128. 8 warps in 4(m) x 2(n).
// smem: casP fragments (16384 u32) + B tile [128k][pitch 136] tf32
// dyn smem = 135168 B
// ---------------------------------------------------------------------------
extern __shared__ uint32_t smu[];

__global__ __launch_bounds__(256, 1)
void casmul_tc(const float* __restrict__ in, float* __restrict__ out,
               const float* __restrict__ addsrc, float scale, int ncols) {
    uint32_t* casS = smu;            // 16384
    uint32_t* bS   = smu + 16384;    // 128 * 136

    const int tid = threadIdx.x;
    const size_t base = (size_t)blockIdx.y * 128u * (size_t)ncols + (size_t)blockIdx.x * 128u;

    // stage cas fragments (64KB)
    #pragma unroll
    for (int i = 0; i < 16; i++)
        ((uint4*)casS)[i*256 + tid] = ((const uint4*)g_casP)[i*256 + tid];

    // load B tile 128x128, convert tf32, pitch 136 (conflict-free: (8k+n)%32)
    #pragma unroll
    for (int it = 0; it < 16; it++) {
        int idx = it*256 + tid;
        int k = idx >> 5, n4 = (idx & 31) << 2;
        float4 v = *(const float4*)&in[base + (size_t)k * (size_t)ncols + n4];
        uint4 u;
        u.x = f2tf(v.x); u.y = f2tf(v.y); u.z = f2tf(v.z); u.w = f2tf(v.w);
        *(uint4*)&bS[k*136 + n4] = u;
    }
    __syncthreads();

    const int w = tid >> 5, lane = tid & 31;
    const int mw = w & 3, nw = w >> 2;
    const int g = lane >> 2, tig = lane & 3;
    const int n0 = nw * 64;

    float acc[2][8][4];
    #pragma unroll
    for (int a = 0; a < 2; a++)
        #pragma unroll
        for (int b = 0; b < 8; b++)
            #pragma unroll
            for (int cc = 0; cc < 4; cc++) acc[a][b][cc] = 0.f;

    #pragma unroll
    for (int ks = 0; ks < 16; ks++) {
        uint4 A0 = ((uint4*)casS)[((mw*2 + 0)*16 + ks)*32 + lane];
        uint4 A1 = ((uint4*)casS)[((mw*2 + 1)*16 + ks)*32 + lane];
        uint32_t b[8][2];
        #pragma unroll
        for (int nf = 0; nf < 8; nf++) {
            int n = n0 + nf*8 + g;
            b[nf][0] = bS[(ks*8 + tig)*136 + n];
            b[nf][1] = bS[(ks*8 + tig + 4)*136 + n];
        }
        #pragma unroll
        for (int nf = 0; nf < 8; nf++) {
            mma8(acc[0][nf], A0.x, A0.y, A0.z, A0.w, b[nf][0], b[nf][1]);
            mma8(acc[1][nf], A1.x, A1.y, A1.z, A1.w, b[nf][0], b[nf][1]);
        }
    }

    // epilogue: scale (+ residual), store float2 pairs
    #pragma unroll
    for (int mf = 0; mf < 2; mf++) {
        int mb = mw*32 + mf*16 + g;
        #pragma unroll
        for (int nf = 0; nf < 8; nf++) {
            int n = n0 + nf*8 + tig*2;
            #pragma unroll
            for (int r = 0; r < 2; r++) {
                size_t o = base + (size_t)(mb + r*8) * (size_t)ncols + n;
                float2 v;
                v.x = acc[mf][nf][r*2 + 0] * scale;
                v.y = acc[mf][nf][r*2 + 1] * scale;
                if (addsrc) {
                    v.x += addsrc[o];
                    v.y += addsrc[o + 1];
                }
                *(float2*)&out[o] = v;
            }
        }
    }
}

// ---------------------------------------------------------------------------
// mlp_tc: per CTA: 128 pixel-rows x one channel-block.
//   O1 = relu(X @ W1 + b1)   [128x128]@[128x256]
//   O2 = O1 @ W2 + b2        [128x256]@[256x128], soft-threshold, store
// smem: X [128][132] tf32 (A-frag conflict-free, pitch%32==4)
//       O1 [128][260] tf32
//       W chunk buffer (max 5120 u32)
// dyn smem = 221184 B
// ---------------------------------------------------------------------------
__global__ __launch_bounds__(256, 1)
void mlp_tc(const float* __restrict__ in, float* __restrict__ out) {
    uint32_t* X  = smu;                    // 128*132 = 16896
    uint32_t* O1 = smu + 16896;            // 128*260 = 33280
    uint32_t* Wb = smu + 16896 + 33280;    // 5120

    const int tid = threadIdx.x;
    const int blk = blockIdx.y;
    const size_t row0 = (size_t)blockIdx.x * 128u;

    // load X tile (128 pixels x 128 channels), convert tf32
    #pragma unroll
    for (int it = 0; it < 16; it++) {
        int idx = it*256 + tid;
        int r = idx >> 5, c4 = (idx & 31) << 2;
        float4 v = *(const float4*)&in[(row0 + r) * CC + blk*BS + c4];
        uint4 u;
        u.x = f2tf(v.x); u.y = f2tf(v.y); u.z = f2tf(v.z); u.w = f2tf(v.w);
        *(uint4*)&X[r*132 + c4] = u;
    }
    __syncthreads();

    const int w = tid >> 5, lane = tid & 31;
    const int g = lane >> 2, tig = lane & 3;
    const int mw = w & 3, nw = w >> 2;     // 4(m) x 2(n)

    // ---------------- GEMM1: n chunks of 32 over HID ----------------
    const uint32_t* W1 = g_w1s + blk*BS*HID;
    for (int ch = 0; ch < 8; ch++) {
        // stage W1[:, ch*32 .. +32] -> Wb [128k][pitch 40]
        #pragma unroll
        for (int it = 0; it < 16; it++) {
            int idx = it*256 + tid;
            int k = idx >> 5, n = idx & 31;
            Wb[k*40 + n] = W1[k*HID + ch*32 + n];
        }
        __syncthreads();

        float acc[2][2][4];
        #pragma unroll
        for (int a = 0; a < 2; a++)
            #pragma unroll
            for (int b = 0; b < 2; b++)
                #pragma unroll
                for (int cc2 = 0; cc2 < 4; cc2++) acc[a][b][cc2] = 0.f;

        #pragma unroll
        for (int ks = 0; ks < 16; ks++) {
            int kk = ks*8;
            uint32_t a[2][4];
            #pragma unroll
            for (int mf = 0; mf < 2; mf++) {
                int m = mw*32 + mf*16;
                a[mf][0] = X[(m + g    )*132 + kk + tig    ];
                a[mf][1] = X[(m + g + 8)*132 + kk + tig    ];
                a[mf][2] = X[(m + g    )*132 + kk + tig + 4];
                a[mf][3] = X[(m + g + 8)*132 + kk + tig + 4];
            }
            uint32_t b[2][2];
            #pragma unroll
            for (int nf = 0; nf < 2; nf++) {
                int n = nw*16 + nf*8 + g;
                b[nf][0] = Wb[(kk + tig    )*40 + n];
                b[nf][1] = Wb[(kk + tig + 4)*40 + n];
            }
            #pragma unroll
            for (int mf = 0; mf < 2; mf++)
                #pragma unroll
                for (int nf = 0; nf < 2; nf++)
                    mma8(acc[mf][nf], a[mf][0], a[mf][1], a[mf][2], a[mf][3], b[nf][0], b[nf][1]);
        }

        // epilogue: bias + relu, write tf32 into O1 [m][nglob], pitch 260
        #pragma unroll
        for (int mf = 0; mf < 2; mf++) {
            #pragma unroll
            for (int nf = 0; nf < 2; nf++) {
                int nglob = ch*32 + nw*16 + nf*8 + tig*2;
                float bx = g_b1s[blk*HID + nglob];
                float by = g_b1s[blk*HID + nglob + 1];
                #pragma unroll
                for (int r = 0; r < 2; r++) {
                    int m = mw*32 + mf*16 + g + r*8;
                    float vx = fmaxf(acc[mf][nf][r*2 + 0] + bx, 0.f);
                    float vy = fmaxf(acc[mf][nf][r*2 + 1] + by, 0.f);
                    O1[m*260 + nglob    ] = f2tf(vx);
                    O1[m*260 + nglob + 1] = f2tf(vy);
                }
            }
        }
        __syncthreads();   // protect Wb restage + O1 completeness on last iter
    }

    // ---------------- GEMM2: k chunks of 32 over HID, n = 128 ----------------
    const uint32_t* W2 = g_w2s + blk*HID*BS;
    float acc2[2][8][4];
    #pragma unroll
    for (int a = 0; a < 2; a++)
        #pragma unroll
        for (int b = 0; b < 8; b++)
            #pragma unroll
            for (int cc2 = 0; cc2 < 4; cc2++) acc2[a][b][cc2] = 0.f;

    for (int ch = 0; ch < 8; ch++) {
        // stage W2[ch*32 .. +32][0..128] -> Wb [32k][pitch 136]
        #pragma unroll
        for (int it = 0; it < 16; it++) {
            int idx = it*256 + tid;
            int k = idx >> 7, n = idx & 127;
            Wb[k*136 + n] = W2[(ch*32 + k)*BS + n];
        }
        __syncthreads();

        #pragma unroll
        for (int ks = 0; ks < 4; ks++) {
            int kk = ks*8;
            uint32_t a[2][4];
            #pragma unroll
            for (int mf = 0; mf < 2; mf++) {
                int m = mw*32 + mf*16;
                a[mf][0] = O1[(m + g    )*260 + ch*32 + kk + tig    ];
                a[mf][1] = O1[(m + g + 8)*260 + ch*32 + kk + tig    ];
                a[mf][2] = O1[(m + g    )*260 + ch*32 + kk + tig + 4];
                a[mf][3] = O1[(m + g + 8)*260 + ch*32 + kk + tig + 4];
            }
            uint32_t b[8][2];
            #pragma unroll
            for (int nf = 0; nf < 8; nf++) {
                int n = nw*64 + nf*8 + g;
                b[nf][0] = Wb[(kk + tig    )*136 + n];
                b[nf][1] = Wb[(kk + tig + 4)*136 + n];
            }
            #pragma unroll
            for (int mf = 0; mf < 2; mf++)
                #pragma unroll
                for (int nf = 0; nf < 8; nf++)
                    mma8(acc2[mf][nf], a[mf][0], a[mf][1], a[mf][2], a[mf][3], b[nf][0], b[nf][1]);
        }
        __syncthreads();   // protect Wb restage
    }

    // epilogue: bias + soft-threshold, store fp32
    #pragma unroll
    for (int mf = 0; mf < 2; mf++) {
        #pragma unroll
        for (int nf = 0; nf < 8; nf++) {
            int n = nw*64 + nf*8 + tig*2;
            float bx = g_b2s[blk*BS + n];
            float by = g_b2s[blk*BS + n + 1];
            #pragma unroll
            for (int r = 0; r < 2; r++) {
                int m = mw*32 + mf*16 + g + r*8;
                float zx = acc2[mf][nf][r*2 + 0] + bx;
                float zy = acc2[mf][nf][r*2 + 1] + by;
                float2 v;
                v.x = (zx > LAM) ? (zx - LAM) : ((zx < -LAM) ? (zx + LAM) : 0.f);
                v.y = (zy > LAM) ? (zy - LAM) : ((zy < -LAM) ? (zy + LAM) : 0.f);
                *(float2*)&out[(row0 + m) * CC + blk*BS + n] = v;
            }
        }
    }
}

// ---------------------------------------------------------------------------
extern "C" void kernel_launch(void* const* d_in, const int* in_sizes, int n_in,
                              void* d_out, int out_size) {
    const float* x  = (const float*)d_in[0];
    const float* w1 = (const float*)d_in[1];
    const float* b1 = (const float*)d_in[2];
    const float* w2 = (const float*)d_in[3];
    const float* b2 = (const float*)d_in[4];
    float* out = (float*)d_out;

    void *p1, *p2;
    cudaGetSymbolAddress(&p1, g_buf1);
    cudaGetSymbolAddress(&p2, g_buf2);
    float* buf1 = (float*)p1;
    float* buf2 = (float*)p2;

    const int CAS_SMEM = (16384 + 128*136) * 4;            // 135168
    const int MLP_SMEM = (128*132 + 128*260 + 5120) * 4;   // 221184
    cudaFuncSetAttribute(casmul_tc, cudaFuncAttributeMaxDynamicSharedMemorySize, CAS_SMEM);
    cudaFuncSetAttribute(mlp_tc,    cudaFuncAttributeMaxDynamicSharedMemorySize, MLP_SMEM);

    prep_kernel<<<1024, 256>>>(w1, b1, w2, b2);

    // forward DHT: along W (batch=B*H, ncols=C), then along H (batch=B, ncols=W*C)
    casmul_tc<<<dim3(CC/128, BB*HH), 256, CAS_SMEM>>>(x,    buf1, nullptr, 1.0f, CC);
    casmul_tc<<<dim3(WW*CC/128, BB), 256, CAS_SMEM>>>(buf1, buf2, nullptr, 1.0f, WW*CC);

    // block MLP + soft threshold
    mlp_tc<<<dim3(BB*HH*WW/128, NB), 256, MLP_SMEM>>>(buf2, buf1);

    // inverse DHT; final pass fuses 1/(H*W) scale + residual add
    casmul_tc<<<dim3(CC/128, BB*HH), 256, CAS_SMEM>>>(buf1, buf2, nullptr, 1.0f, CC);
    casmul_tc<<<dim3(WW*CC/128, BB), 256, CAS_SMEM>>>(buf2, out, x, 1.0f/(HH*WW), WW*CC);
}

// round 3
// speedup vs baseline: 3.4008x; 1.3216x over previous
#include <cuda_runtime.h>
#include <stdint.h>

#define BB 4
#define HH 128
#define WW 128
#define CC 1024
#define NB 8
#define BS 128
#define HID 256
#define LAM 0.01f
#define NTOT (BB*HH*WW*CC)

// ---------------- scratch (device .bss, no allocation) ----------------
__device__ __align__(128) float g_buf1[NTOT];
__device__ __align__(128) float g_buf2[NTOT];
// cas matrix in mma A-fragment layout (raw fp32 bits; HMMA.tf32 truncates):
// frag t = (mt*16 + ks)*32 + lane ; 4 regs each
__device__ __align__(16) uint32_t g_casP[8*16*32*4];
__device__ __align__(16) uint32_t g_w1s[NB*BS*HID];   // folded [blk][i=128][o=256]
__device__ __align__(16) uint32_t g_w2s[NB*HID*BS];   // folded [blk][o=256][i=128]
__device__ float g_b1s[NB*HID];
__device__ float g_b2s[NB*BS];

// ---------------- helpers ----------------
__device__ __forceinline__ void mma8(float* c, uint32_t a0, uint32_t a1, uint32_t a2, uint32_t a3,
                                     uint32_t b0, uint32_t b1) {
    asm volatile("mma.sync.aligned.m16n8k8.row.col.f32.tf32.tf32.f32 "
                 "{%0,%1,%2,%3}, {%4,%5,%6,%7}, {%8,%9}, {%0,%1,%2,%3};"
                 : "+f"(c[0]), "+f"(c[1]), "+f"(c[2]), "+f"(c[3])
                 : "r"(a0), "r"(a1), "r"(a2), "r"(a3), "r"(b0), "r"(b1));
}
__device__ __forceinline__ void cp16(uint32_t saddr, const void* gptr) {
    asm volatile("cp.async.cg.shared.global [%0], [%1], 16;" :: "r"(saddr), "l"(gptr));
}
#define CP_COMMIT() asm volatile("cp.async.commit_group;")
#define CP_WAIT1()  asm volatile("cp.async.wait_group 1;")

// ---------------- prep ----------------
__device__ __forceinline__ float casv(int m, int k) {
    float s, c;
    sincospif((float)((m * k) & 127) * (1.0f/64.0f), &s, &c);
    return c + s;
}

__global__ void prep_kernel(const float* __restrict__ w1, const float* __restrict__ b1,
                            const float* __restrict__ w2, const float* __restrict__ b2) {
    int t = blockIdx.x * blockDim.x + threadIdx.x;
    if (t < 8*16*32) {
        int lane = t & 31, ks = (t >> 5) & 15, mt = t >> 9;
        int g = lane >> 2, kk = ks*8 + (lane & 3);
        int m0 = mt*16 + g;
        uint32_t* d = &g_casP[t*4];
        d[0] = __float_as_uint(casv(m0,     kk));
        d[1] = __float_as_uint(casv(m0 + 8, kk));
        d[2] = __float_as_uint(casv(m0,     kk + 4));
        d[3] = __float_as_uint(casv(m0 + 8, kk + 4));
    }
    if (t < NB*BS*HID) {
        g_w1s[t] = __float_as_uint(w1[t] + w1[NB*BS*HID + t]);
        g_w2s[t] = __float_as_uint(w2[t] + w2[NB*HID*BS + t]);
    }
    if (t < NB*HID) g_b1s[t] = b1[t];
    if (t < NB*BS)  g_b2s[t] = b2[t];
}

// ---------------------------------------------------------------------------
// casmul_p: persistent. OUT[bt, m, n] = scale * sum_k cas[m,k] IN[bt, k, n] (+add)
// Tile: 128m x 64n x 128k. 8 warps, warp w owns A rows [16w,16w+16) in regs.
// smem: double-buffered B tile [2][128][72] u32 = 73728 B. cp.async pipelined.
// ---------------------------------------------------------------------------
extern __shared__ uint32_t smu[];

__global__ __launch_bounds__(256, 2)
void casmul_p(const float* __restrict__ in, float* __restrict__ out,
              const float* __restrict__ addsrc, float scale, int ncols, int total) {
    const int tid = threadIdx.x;
    const int w = tid >> 5, lane = tid & 31;
    const int g = lane >> 2, tig = lane & 3;
    const int ntn = ncols >> 6;          // tiles along n

    // A fragments: warp w covers mt = w (rows 16w..16w+15), all 16 k-steps
    uint4 A[16];
    {
        const uint4* gA = (const uint4*)g_casP;
        #pragma unroll
        for (int ks = 0; ks < 16; ks++)
            A[ks] = __ldg(&gA[(w*16 + ks)*32 + lane]);
    }

    uint32_t* bS0 = smu;          // [128][72]
    uint32_t* bS1 = smu + 9216;

    // prefetch tile for t = blockIdx.x into buf0
    int t = blockIdx.x;
    {
        int bt = t / ntn, nb = t - bt*ntn;
        const float* src = in + (size_t)bt * 128u * (size_t)ncols + nb*64;
        #pragma unroll
        for (int i = 0; i < 8; i++) {
            int idx = i*256 + tid;
            int k = idx >> 4, n4 = (idx & 15) << 2;
            uint32_t sa = (uint32_t)__cvta_generic_to_shared(&bS0[k*72 + n4]);
            cp16(sa, src + (size_t)k * (size_t)ncols + n4);
        }
    }
    CP_COMMIT();

    int buf = 0;
    for (; t < total; t += gridDim.x) {
        // prefetch next tile into other buffer
        int tn = t + gridDim.x;
        if (tn < total) {
            uint32_t* bN = buf ? bS0 : bS1;
            int bt = tn / ntn, nb = tn - bt*ntn;
            const float* src = in + (size_t)bt * 128u * (size_t)ncols + nb*64;
            #pragma unroll
            for (int i = 0; i < 8; i++) {
                int idx = i*256 + tid;
                int k = idx >> 4, n4 = (idx & 15) << 2;
                uint32_t sa = (uint32_t)__cvta_generic_to_shared(&bN[k*72 + n4]);
                cp16(sa, src + (size_t)k * (size_t)ncols + n4);
            }
        }
        CP_COMMIT();
        CP_WAIT1();
        __syncthreads();

        const uint32_t* bS = buf ? bS1 : bS0;
        float acc[8][4];
        #pragma unroll
        for (int i = 0; i < 8; i++)
            #pragma unroll
            for (int j = 0; j < 4; j++) acc[i][j] = 0.f;

        #pragma unroll
        for (int ks = 0; ks < 16; ks++) {
            uint32_t b[8][2];
            #pragma unroll
            for (int nf = 0; nf < 8; nf++) {
                int n = nf*8 + g;
                b[nf][0] = bS[(ks*8 + tig    )*72 + n];
                b[nf][1] = bS[(ks*8 + tig + 4)*72 + n];
            }
            #pragma unroll
            for (int nf = 0; nf < 8; nf++)
                mma8(acc[nf], A[ks].x, A[ks].y, A[ks].z, A[ks].w, b[nf][0], b[nf][1]);
        }

        // epilogue
        {
            int bt = t / ntn, nb = t - bt*ntn;
            const size_t base = (size_t)bt * 128u * (size_t)ncols + nb*64;
            #pragma unroll
            for (int nf = 0; nf < 8; nf++) {
                int col = nf*8 + tig*2;
                #pragma unroll
                for (int r = 0; r < 2; r++) {
                    int row = w*16 + g + r*8;
                    size_t o = base + (size_t)row * (size_t)ncols + col;
                    float2 v;
                    v.x = acc[nf][r*2 + 0] * scale;
                    v.y = acc[nf][r*2 + 1] * scale;
                    if (addsrc) { v.x += addsrc[o]; v.y += addsrc[o + 1]; }
                    *(float2*)&out[o] = v;
                }
            }
        }
        __syncthreads();   // all reads of this buffer done before it is re-prefetched
        buf ^= 1;
    }
}

// ---------------------------------------------------------------------------
// mlp_tc: 128 pixels x one channel block per CTA, fused chunk loop.
//   for ch in 0..7 (32 hidden each):
//     O1ch = relu(X @ W1[:,ch] + b1[ch]); acc2 += O1ch @ W2[ch,:]
// smem: X[128][132] + O1ch[128][36] + Wb[5120]  = 106496 B  -> 2 CTAs/SM
// ---------------------------------------------------------------------------
__global__ __launch_bounds__(256, 2)
void mlp_tc(const float* __restrict__ in, float* __restrict__ out) {
    uint32_t* X    = smu;                  // 16896
    uint32_t* O1ch = smu + 16896;          // 128*36 = 4608
    uint32_t* Wb   = smu + 16896 + 4608;   // 5120

    const int tid = threadIdx.x;
    const int blk = blockIdx.y;
    const size_t row0 = (size_t)blockIdx.x * 128u;

    // load X tile (raw fp32 bits)
    #pragma unroll
    for (int it = 0; it < 16; it++) {
        int idx = it*256 + tid;
        int r = idx >> 5, c4 = (idx & 31) << 2;
        *(uint4*)&X[r*132 + c4] =
            *(const uint4*)&in[(row0 + r) * CC + blk*BS + c4];
    }

    const int w = tid >> 5, lane = tid & 31;
    const int g = lane >> 2, tig = lane & 3;
    const int mw = w & 3, nw = w >> 2;     // 4(m) x 2(n)

    const uint32_t* W1 = g_w1s + blk*BS*HID;
    const uint32_t* W2 = g_w2s + blk*HID*BS;

    float acc2[2][8][4];
    #pragma unroll
    for (int a = 0; a < 2; a++)
        #pragma unroll
        for (int b = 0; b < 8; b++)
            #pragma unroll
            for (int c = 0; c < 4; c++) acc2[a][b][c] = 0.f;

    __syncthreads();   // X ready

    for (int ch = 0; ch < 8; ch++) {
        // ---- stage W1 chunk: [128k][32n] pitch 40 ----
        #pragma unroll
        for (int it = 0; it < 16; it++) {
            int idx = it*256 + tid;
            int k = idx >> 5, n = idx & 31;
            Wb[k*40 + n] = W1[k*HID + ch*32 + n];
        }
        __syncthreads();

        // ---- GEMM1 chunk: [128,128]@[128,32] ----
        float acc1[2][2][4];
        #pragma unroll
        for (int a = 0; a < 2; a++)
            #pragma unroll
            for (int b = 0; b < 2; b++)
                #pragma unroll
                for (int c = 0; c < 4; c++) acc1[a][b][c] = 0.f;

        #pragma unroll
        for (int ks = 0; ks < 16; ks++) {
            int kk = ks*8;
            uint32_t a[2][4];
            #pragma unroll
            for (int mf = 0; mf < 2; mf++) {
                int m = mw*32 + mf*16;
                a[mf][0] = X[(m + g    )*132 + kk + tig    ];
                a[mf][1] = X[(m + g + 8)*132 + kk + tig    ];
                a[mf][2] = X[(m + g    )*132 + kk + tig + 4];
                a[mf][3] = X[(m + g + 8)*132 + kk + tig + 4];
            }
            uint32_t b[2][2];
            #pragma unroll
            for (int nf = 0; nf < 2; nf++) {
                int n = nw*16 + nf*8 + g;
                b[nf][0] = Wb[(kk + tig    )*40 + n];
                b[nf][1] = Wb[(kk + tig + 4)*40 + n];
            }
            #pragma unroll
            for (int mf = 0; mf < 2; mf++)
                #pragma unroll
                for (int nf = 0; nf < 2; nf++)
                    mma8(acc1[mf][nf], a[mf][0], a[mf][1], a[mf][2], a[mf][3], b[nf][0], b[nf][1]);
        }

        // ---- bias + relu -> O1ch (pitch 36) ----
        #pragma unroll
        for (int mf = 0; mf < 2; mf++) {
            #pragma unroll
            for (int nf = 0; nf < 2; nf++) {
                int nc = nw*16 + nf*8 + tig*2;           // col within chunk
                float bx = g_b1s[blk*HID + ch*32 + nc];
                float by = g_b1s[blk*HID + ch*32 + nc + 1];
                #pragma unroll
                for (int r = 0; r < 2; r++) {
                    int m = mw*32 + mf*16 + g + r*8;
                    float vx = fmaxf(acc1[mf][nf][r*2 + 0] + bx, 0.f);
                    float vy = fmaxf(acc1[mf][nf][r*2 + 1] + by, 0.f);
                    O1ch[m*36 + nc    ] = __float_as_uint(vx);
                    O1ch[m*36 + nc + 1] = __float_as_uint(vy);
                }
            }
        }
        __syncthreads();   // O1ch complete; Wb free for restage

        // ---- stage W2 chunk: [32k][128n] pitch 136 ----
        #pragma unroll
        for (int it = 0; it < 16; it++) {
            int idx = it*256 + tid;
            int k = idx >> 7, n = idx & 127;
            Wb[k*136 + n] = W2[(ch*32 + k)*BS + n];
        }
        __syncthreads();

        // ---- GEMM2 partial: [128,32]@[32,128] accumulate ----
        #pragma unroll
        for (int ks = 0; ks < 4; ks++) {
            int kk = ks*8;
            uint32_t a[2][4];
            #pragma unroll
            for (int mf = 0; mf < 2; mf++) {
                int m = mw*32 + mf*16;
                a[mf][0] = O1ch[(m + g    )*36 + kk + tig    ];
                a[mf][1] = O1ch[(m + g + 8)*36 + kk + tig    ];
                a[mf][2] = O1ch[(m + g    )*36 + kk + tig + 4];
                a[mf][3] = O1ch[(m + g + 8)*36 + kk + tig + 4];
            }
            uint32_t b[8][2];
            #pragma unroll
            for (int nf = 0; nf < 8; nf++) {
                int n = nw*64 + nf*8 + g;
                b[nf][0] = Wb[(kk + tig    )*136 + n];
                b[nf][1] = Wb[(kk + tig + 4)*136 + n];
            }
            #pragma unroll
            for (int mf = 0; mf < 2; mf++)
                #pragma unroll
                for (int nf = 0; nf < 8; nf++)
                    mma8(acc2[mf][nf], a[mf][0], a[mf][1], a[mf][2], a[mf][3], b[nf][0], b[nf][1]);
        }
        __syncthreads();   // done reading Wb/O1ch before next chunk overwrites
    }

    // ---- epilogue: bias + soft-threshold ----
    #pragma unroll
    for (int mf = 0; mf < 2; mf++) {
        #pragma unroll
        for (int nf = 0; nf < 8; nf++) {
            int n = nw*64 + nf*8 + tig*2;
            float bx = g_b2s[blk*BS + n];
            float by = g_b2s[blk*BS + n + 1];
            #pragma unroll
            for (int r = 0; r < 2; r++) {
                int m = mw*32 + mf*16 + g + r*8;
                float zx = acc2[mf][nf][r*2 + 0] + bx;
                float zy = acc2[mf][nf][r*2 + 1] + by;
                float2 v;
                v.x = (zx > LAM) ? (zx - LAM) : ((zx < -LAM) ? (zx + LAM) : 0.f);
                v.y = (zy > LAM) ? (zy - LAM) : ((zy < -LAM) ? (zy + LAM) : 0.f);
                *(float2*)&out[(row0 + m) * CC + blk*BS + n] = v;
            }
        }
    }
}

// ---------------------------------------------------------------------------
extern "C" void kernel_launch(void* const* d_in, const int* in_sizes, int n_in,
                              void* d_out, int out_size) {
    const float* x  = (const float*)d_in[0];
    const float* w1 = (const float*)d_in[1];
    const float* b1 = (const float*)d_in[2];
    const float* w2 = (const float*)d_in[3];
    const float* b2 = (const float*)d_in[4];
    float* out = (float*)d_out;

    void *p1, *p2;
    cudaGetSymbolAddress(&p1, g_buf1);
    cudaGetSymbolAddress(&p2, g_buf2);
    float* buf1 = (float*)p1;
    float* buf2 = (float*)p2;

    const int CAS_SMEM = 2 * 128 * 72 * 4;                 // 73728
    const int MLP_SMEM = (16896 + 4608 + 5120) * 4;        // 106496
    cudaFuncSetAttribute(casmul_p, cudaFuncAttributeMaxDynamicSharedMemorySize, CAS_SMEM);
    cudaFuncSetAttribute(mlp_tc,   cudaFuncAttributeMaxDynamicSharedMemorySize, MLP_SMEM);

    prep_kernel<<<1024, 256>>>(w1, b1, w2, b2);

    const int GRID = 296;   // 2 CTAs/SM persistent
    const int T1 = (CC/64) * (BB*HH);      // 8192 tiles (transform along W)
    const int T2 = (WW*CC/64) * BB;        // 8192 tiles (transform along H)

    casmul_p<<<GRID, 256, CAS_SMEM>>>(x,    buf1, nullptr, 1.0f, CC,    T1);
    casmul_p<<<GRID, 256, CAS_SMEM>>>(buf1, buf2, nullptr, 1.0f, WW*CC, T2);

    mlp_tc<<<dim3(BB*HH*WW/128, NB), 256, MLP_SMEM>>>(buf2, buf1);

    casmul_p<<<GRID, 256, CAS_SMEM>>>(buf1, buf2, nullptr, 1.0f, CC,    T1);
    casmul_p<<<GRID, 256, CAS_SMEM>>>(buf2, out, x, 1.0f/(HH*WW), WW*CC, T2);
}